// round 11
// baseline (speedup 1.0000x reference)
#include <cuda_runtime.h>

#define Cc 128
#define Hh 128
#define Ww 256
#define Bb 8
#define Kk 9
#define CSTRIDE (Hh * Ww)          // 32768
#define BSTRIDE (Cc * Hh * Ww)     // 4194304

typedef unsigned long long ull;

// Per-(batch, p-block, co-block, step) completion flags. Reset per pass.
__device__ unsigned g_flag[Bb][4][4][256];
// Transposed-state scratch: [b][c][w][h]
__device__ float g_tmp[(size_t)Bb * BSTRIDE];

// ---------- f32x2 helpers ----------
__device__ __forceinline__ void fma2(ull& d, ull a, ull b) {
    asm("fma.rn.f32x2 %0, %1, %2, %0;" : "+l"(d) : "l"(a), "l"(b));
}
__device__ __forceinline__ float2 unpack2(ull v) {
    float2 f;
    asm("mov.b64 {%0, %1}, %2;" : "=f"(f.x), "=f"(f.y) : "l"(v));
    return f;
}
__device__ __forceinline__ unsigned ld_cg_u32(const unsigned* p) {
    unsigned v;
    asm volatile("ld.global.cg.u32 %0, [%1];" : "=r"(v) : "l"(p));
    return v;
}
__device__ __forceinline__ void group_bar(int id, int cnt) {
    asm volatile("bar.sync %0, %1;" :: "r"(id), "r"(cnt) : "memory");
}

// Persistent directional pass; 512 threads = 4 ci-groups (SPLIT=4) of 128.
// Group sp owns ci slice [32sp, 32sp+32) (== co-block sp of the producer row),
// waits only on its producers' flags, stages its slice, computes partials.
// One CTA-wide __syncthreads per step before the cross-split reduction; sp0
// reduces + epilogue + publishes while other groups start step s+1.
//
// Register tiling (128 regs/thread @512 thr): COT=2 co x TP p outputs.
// acc u64 lanes pack (even-ci, odd-ci) partials; conv = lane0+lane1.
// Weights streamed per-k: one LDS.128 -> (w[co0][k], w[co1][k]) as 2 u64.
template <int TP, int SPLIT>
__global__ __launch_bounds__(512, 1)
void pass_kernel(float* __restrict__ state, const float* __restrict__ wt,
                 int q0, int dq, int nq, int L, int SQ)
{
    constexpr int COT    = 2;
    constexpr int CGC    = 16;                  // co-groups (16 x 2 co = 32)
    constexpr int PGC    = 512 / SPLIT / CGC;   // 8 p-groups
    constexpr int PT     = PGC * TP;            // CTA p extent (W:64, H:32)
    constexpr int WIN    = PT + 8;              // u64 window entries per ci2
    constexpr int NW     = TP + 8;              // per-thread window u64s
    constexpr int G      = 512 / SPLIT;         // 128 threads per ci-group
    constexpr int ROWU64 = Kk * COT;            // 18 weight u64 per (cg,ci2)
    constexpr int WU64   = CGC * 64 * ROWU64;   // 18432
    constexpr int CI2PER = 64 / SPLIT;          // 16
    constexpr int SCH    = WIN / 4;             // float4 stage chunks per ci2
    constexpr int ACCN   = COT * TP;            // 16 (W) / 8 (H)

    extern __shared__ ull smu[];
    ull*   s_w   = smu;                          // paired weights
    ull*   s_in  = smu + WU64;                   // [64 ci2][WIN]
    float* s_red = reinterpret_cast<float*>(s_in + 64 * WIN);

    const int tid  = threadIdx.x;
    const int sp   = tid / G;
    const int gtid = tid & (G - 1);
    const int pg   = gtid & (PGC - 1);
    const int cg   = gtid / PGC;

    const int px  = blockIdx.x;
    const int cby = blockIdx.y;
    const int b   = blockIdx.z;
    const int p0  = px * PT;
    const int co0 = cby * 32;
    const int npx = gridDim.x;
    float* base = state + (long)b * BSTRIDE;

    // ---- stage paired weights once per pass ----
    {
        float* s_wf = reinterpret_cast<float*>(s_w);
        for (int idx = tid; idx < CGC * 64 * Kk * COT; idx += 512) {
            int c   = idx % COT;
            int k   = (idx / COT) % Kk;
            int ci2 = (idx / (COT * Kk)) % 64;
            int cgi = idx / (COT * Kk * 64);
            int co  = co0 + cgi * COT + c;
            long u  = (long)cgi * (64 * ROWU64) + ci2 * ROWU64 + k * COT + c;
            s_wf[u * 2 + 0] = wt[(long)co * (Cc * Kk) + (2 * ci2) * Kk + k];
            s_wf[u * 2 + 1] = wt[(long)co * (Cc * Kk) + (2 * ci2 + 1) * Kk + k];
        }
    }
    __syncthreads();

    const ull* wbase = s_w + (long)cg * (64 * ROWU64);
    const int ci2lo = sp * CI2PER;
    const int cbs   = sp;            // producer co-block of this ci slice

    for (int s = 1; s < nq; s++) {
        const int q = q0 + s * dq;
        const float* prev = base + (long)(q - dq) * SQ;
        float*       cur  = base + (long)q * SQ;
        const long oBase = (long)(co0 + cg * COT) * CSTRIDE + p0 + pg * TP;

        // ---- prefetch cur_old (pass-stable; sp0 only) ----
        float4 oldv[COT][TP / 4];
        if (sp == 0) {
#pragma unroll
            for (int c = 0; c < COT; c++)
#pragma unroll
                for (int j = 0; j < TP / 4; j++)
                    oldv[c][j] = __ldcg(reinterpret_cast<const float4*>(
                        cur + oBase + (long)c * CSTRIDE + j * 4));
        }

        // ---- wait for this slice's producers (+ own CTA for s_red guard) ----
        if (s > 1 && gtid < 4) {
            const unsigned* f = nullptr;
            if (gtid < 3) {
                int pxn = px + gtid - 1;
                if (pxn >= 0 && pxn < npx) f = &g_flag[b][pxn][cbs][s - 1];
            } else {
                f = &g_flag[b][px][cby][s - 1];
            }
            if (f) {
                while (ld_cg_u32(f) == 0u) __nanosleep(20);
                __threadfence();
            }
        }
        group_bar(sp + 1, G);

        // ---- stage own ci2 slice of the window ----
        for (int t = gtid; t < CI2PER * SCH; t += G) {
            const int ci2 = ci2lo + t / SCH;
            const int c4  = t % SCH;
            const int p   = p0 - 4 + c4 * 4;
            const float* sa = prev + (long)(2 * ci2) * CSTRIDE + p;
            const float* sb = sa + CSTRIDE;
            float4 a, bb;
            if (p >= 0 && p + 4 <= L) {
                a  = __ldcg(reinterpret_cast<const float4*>(sa));
                bb = __ldcg(reinterpret_cast<const float4*>(sb));
            } else {
                a.x = (unsigned)(p+0) < (unsigned)L ? __ldcg(sa+0) : 0.f;
                a.y = (unsigned)(p+1) < (unsigned)L ? __ldcg(sa+1) : 0.f;
                a.z = (unsigned)(p+2) < (unsigned)L ? __ldcg(sa+2) : 0.f;
                a.w = (unsigned)(p+3) < (unsigned)L ? __ldcg(sa+3) : 0.f;
                bb.x = (unsigned)(p+0) < (unsigned)L ? __ldcg(sb+0) : 0.f;
                bb.y = (unsigned)(p+1) < (unsigned)L ? __ldcg(sb+1) : 0.f;
                bb.z = (unsigned)(p+2) < (unsigned)L ? __ldcg(sb+2) : 0.f;
                bb.w = (unsigned)(p+3) < (unsigned)L ? __ldcg(sb+3) : 0.f;
            }
            float4* s4 = reinterpret_cast<float4*>(s_in);
            const int f4i = (ci2 * WIN + c4 * 4) >> 1;
            s4[f4i + 0] = make_float4(a.x, bb.x, a.y, bb.y);
            s4[f4i + 1] = make_float4(a.z, bb.z, a.w, bb.w);
        }
        group_bar(sp + 1, G);

        // ---- register-tiled compute over own ci2 slice ----
        ull acc[COT][TP];
#pragma unroll
        for (int c = 0; c < COT; c++)
#pragma unroll
            for (int pt = 0; pt < TP; pt++) acc[c][pt] = 0ull;

#pragma unroll 2
        for (int i = 0; i < CI2PER; i++) {
            const int ci2 = ci2lo + i;
            ull win[NW];
            {
                const ulonglong2* w2 = reinterpret_cast<const ulonglong2*>(
                    s_in + (long)ci2 * WIN + pg * TP);
#pragma unroll
                for (int j = 0; j < NW / 2; j++) {
                    ulonglong2 t = w2[j];
                    win[2 * j] = t.x; win[2 * j + 1] = t.y;
                }
            }
            const ull* wrow = wbase + (long)ci2 * ROWU64;
#pragma unroll
            for (int k = 0; k < Kk; k++) {
                ulonglong2 w = *reinterpret_cast<const ulonglong2*>(wrow + k * 2);
#pragma unroll
                for (int pt = 0; pt < TP; pt++) {
                    fma2(acc[0][pt], w.x, win[pt + k]);
                    fma2(acc[1][pt], w.y, win[pt + k]);
                }
            }
        }

        // ---- fold lanes to floats; sp>0 deposit partials ----
        float f[ACCN];
#pragma unroll
        for (int c = 0; c < COT; c++)
#pragma unroll
            for (int pt = 0; pt < TP; pt++) {
                float2 t = unpack2(acc[c][pt]);
                f[c * TP + pt] = t.x + t.y;
            }
        if (sp > 0) {
            float* r = s_red + (long)((sp - 1) * G + gtid) * ACCN;
#pragma unroll
            for (int j = 0; j < ACCN / 4; j++)
                *reinterpret_cast<float4*>(r + j * 4) =
                    make_float4(f[j*4], f[j*4+1], f[j*4+2], f[j*4+3]);
        }
        __syncthreads();   // the ONLY CTA-wide barrier per step

        if (sp == 0) {
#pragma unroll
            for (int j = 0; j < SPLIT - 1; j++) {
                const float* r = s_red + (long)(j * G + gtid) * ACCN;
#pragma unroll
                for (int t = 0; t < ACCN / 4; t++) {
                    float4 rv = *reinterpret_cast<const float4*>(r + t * 4);
                    f[t*4]   += rv.x; f[t*4+1] += rv.y;
                    f[t*4+2] += rv.z; f[t*4+3] += rv.w;
                }
            }
            // ---- epilogue: cur = cur_old + relu(conv) ----
#pragma unroll
            for (int c = 0; c < COT; c++) {
                float* op = cur + oBase + (long)c * CSTRIDE;
#pragma unroll
                for (int j = 0; j < TP / 4; j++) {
                    float4 e;
                    e.x = oldv[c][j].x + fmaxf(f[c*TP + j*4 + 0], 0.f);
                    e.y = oldv[c][j].y + fmaxf(f[c*TP + j*4 + 1], 0.f);
                    e.z = oldv[c][j].z + fmaxf(f[c*TP + j*4 + 2], 0.f);
                    e.w = oldv[c][j].w + fmaxf(f[c*TP + j*4 + 3], 0.f);
                    *reinterpret_cast<float4*>(op + j * 4) = e;
                }
            }
            group_bar(1, G);
            if (tid == 0) {
                __threadfence();
                atomicExch(&g_flag[b][px][cby][s], 1u);
            }
        }
    }
}

// [b,c,R,C] -> [b,c,C,R], tiled 32x32.
__global__ __launch_bounds__(256)
void transpose_kernel(const float* __restrict__ src, float* __restrict__ dst,
                      int R, int C)
{
    __shared__ float t[32][33];
    const long plane = blockIdx.z;
    const float* s = src + plane * (long)R * C;
    float*       d = dst + plane * (long)R * C;
    const int c0 = blockIdx.x * 32, r0 = blockIdx.y * 32;
    const int x = threadIdx.x & 31, y = threadIdx.x >> 5;
#pragma unroll
    for (int i = 0; i < 32; i += 8)
        t[y + i][x] = s[(long)(r0 + y + i) * C + c0 + x];
    __syncthreads();
#pragma unroll
    for (int i = 0; i < 32; i += 8)
        d[(long)(c0 + y + i) * R + r0 + x] = t[x][y + i];
}

extern "C" void kernel_launch(void* const* d_in, const int* in_sizes, int n_in,
                              void* d_out, int out_size)
{
    const float* x       = (const float*)d_in[0];
    const float* w_down  = (const float*)d_in[1];
    const float* w_up    = (const float*)d_in[2];
    const float* w_right = (const float*)d_in[3];
    const float* w_left  = (const float*)d_in[4];
    float* out = (float*)d_out;

    // SMEM: weights 18432 u64 + window 64*WIN u64 + s_red floats
    const int SMEM_W = 18432 * 8 + 64 * 72 * 8 + 3 * 128 * 16 * 4;  // 208896
    const int SMEM_H = 18432 * 8 + 64 * 40 * 8 + 3 * 128 * 8 * 4;   // 180224
    cudaFuncSetAttribute((const void*)pass_kernel<8, 4>,
                         cudaFuncAttributeMaxDynamicSharedMemorySize, SMEM_W);
    cudaFuncSetAttribute((const void*)pass_kernel<4, 4>,
                         cudaFuncAttributeMaxDynamicSharedMemorySize, SMEM_H);

    void* flagp = nullptr; cudaGetSymbolAddress(&flagp, g_flag);
    void* tmpp  = nullptr; cudaGetSymbolAddress(&tmpp, g_tmp);
    float* tmp = (float*)tmpp;
    const size_t FLAG_BYTES = sizeof(unsigned) * Bb * 4 * 4 * 256;

    cudaMemcpyAsync(out, x, (size_t)Bb * BSTRIDE * sizeof(float),
                    cudaMemcpyDeviceToDevice);

    dim3 blk(512);
    dim3 gridW(Ww / 64, Cc / 32, Bb);   // conv along W: TP=8, PT=64
    dim3 gridH(Hh / 32, Cc / 32, Bb);   // conv along H: TP=4, PT=32

    // Pass 1: down. [b,c,h,w]: conv axis w (L=256), rec over h (SQ=256).
    cudaMemsetAsync(flagp, 0, FLAG_BYTES);
    pass_kernel<8, 4><<<gridW, blk, SMEM_W>>>(out, w_down, 0, +1, Hh, Ww, Ww);

    // Pass 2: up.
    cudaMemsetAsync(flagp, 0, FLAG_BYTES);
    pass_kernel<8, 4><<<gridW, blk, SMEM_W>>>(out, w_up, Hh - 1, -1, Hh, Ww, Ww);

    // Transpose to [b,c,w,h]
    transpose_kernel<<<dim3(Ww / 32, Hh / 32, Bb * Cc), dim3(256)>>>(out, tmp, Hh, Ww);

    // Pass 3: right. conv axis h (L=128), rec over w (SQ=128).
    cudaMemsetAsync(flagp, 0, FLAG_BYTES);
    pass_kernel<4, 4><<<gridH, blk, SMEM_H>>>(tmp, w_right, 0, +1, Ww, Hh, Hh);

    // Pass 4: left.
    cudaMemsetAsync(flagp, 0, FLAG_BYTES);
    pass_kernel<4, 4><<<gridH, blk, SMEM_H>>>(tmp, w_left, Ww - 1, -1, Ww, Hh, Hh);

    // Transpose back to [b,c,h,w]
    transpose_kernel<<<dim3(Hh / 32, Ww / 32, Bb * Cc), dim3(256)>>>(tmp, out, Ww, Hh);
}

// round 12
// speedup vs baseline: 1.0031x; 1.0031x over previous
#include <cuda_runtime.h>

#define Cc 128
#define Hh 128
#define Ww 256
#define Bb 8
#define Kk 9
#define CSTRIDE (Hh * Ww)          // 32768
#define BSTRIDE (Cc * Hh * Ww)     // 4194304

typedef unsigned long long ull;

// Per-(batch, p-block, co-block, step) completion flags. Reset per pass.
__device__ unsigned g_flag[Bb][4][4][256];
// Transposed-state scratch: [b][c][w][h]
__device__ float g_tmp[(size_t)Bb * BSTRIDE];

// ---------- f32x2 helpers ----------
__device__ __forceinline__ void fma2(ull& d, ull a, ull b) {
    asm("fma.rn.f32x2 %0, %1, %2, %0;" : "+l"(d) : "l"(a), "l"(b));
}
__device__ __forceinline__ float2 unpack2(ull v) {
    float2 f;
    asm("mov.b64 {%0, %1}, %2;" : "=f"(f.x), "=f"(f.y) : "l"(v));
    return f;
}
__device__ __forceinline__ unsigned ld_cg_u32(const unsigned* p) {
    unsigned v;
    asm volatile("ld.global.cg.u32 %0, [%1];" : "=r"(v) : "l"(p));
    return v;
}
__device__ __forceinline__ void group_bar(int id, int cnt) {
    asm volatile("bar.sync %0, %1;" :: "r"(id), "r"(cnt) : "memory");
}

// Persistent directional pass; 512 threads = 4 ci-groups (SPLIT=4) of 128.
// Group sp owns ci slice [32sp, 32sp+32) (== co-block sp of the producer row),
// waits only on its producers' flags, stages its slice, computes partials.
// One CTA-wide __syncthreads per step before the cross-split reduction; sp0
// reduces + epilogue + publishes while other groups start step s+1.
//
// Register tiling (128 regs/thread @512 thr): COT=2 co x TP p outputs.
// acc u64 lanes pack (even-ci, odd-ci) partials; conv = lane0+lane1.
// Weights streamed per-k: one LDS.128 -> (w[co0][k], w[co1][k]) as 2 u64.
template <int TP, int SPLIT>
__global__ __launch_bounds__(512, 1)
void pass_kernel(float* __restrict__ state, const float* __restrict__ wt,
                 int q0, int dq, int nq, int L, int SQ)
{
    constexpr int COT    = 2;
    constexpr int CGC    = 16;                  // co-groups (16 x 2 co = 32)
    constexpr int PGC    = 512 / SPLIT / CGC;   // 8 p-groups
    constexpr int PT     = PGC * TP;            // CTA p extent (W:64, H:32)
    constexpr int WIN    = PT + 8;              // u64 window entries per ci2
    constexpr int NW     = TP + 8;              // per-thread window u64s
    constexpr int G      = 512 / SPLIT;         // 128 threads per ci-group
    constexpr int ROWU64 = Kk * COT;            // 18 weight u64 per (cg,ci2)
    constexpr int WU64   = CGC * 64 * ROWU64;   // 18432
    constexpr int CI2PER = 64 / SPLIT;          // 16
    constexpr int SCH    = WIN / 4;             // float4 stage chunks per ci2
    constexpr int ACCN   = COT * TP;            // 16 (W) / 8 (H)

    extern __shared__ ull smu[];
    ull*   s_w   = smu;                          // paired weights
    ull*   s_in  = smu + WU64;                   // [64 ci2][WIN]
    float* s_red = reinterpret_cast<float*>(s_in + 64 * WIN);

    const int tid  = threadIdx.x;
    const int sp   = tid / G;
    const int gtid = tid & (G - 1);
    const int pg   = gtid & (PGC - 1);
    const int cg   = gtid / PGC;

    const int px  = blockIdx.x;
    const int cby = blockIdx.y;
    const int b   = blockIdx.z;
    const int p0  = px * PT;
    const int co0 = cby * 32;
    const int npx = gridDim.x;
    float* base = state + (long)b * BSTRIDE;

    // ---- stage paired weights once per pass ----
    {
        float* s_wf = reinterpret_cast<float*>(s_w);
        for (int idx = tid; idx < CGC * 64 * Kk * COT; idx += 512) {
            int c   = idx % COT;
            int k   = (idx / COT) % Kk;
            int ci2 = (idx / (COT * Kk)) % 64;
            int cgi = idx / (COT * Kk * 64);
            int co  = co0 + cgi * COT + c;
            long u  = (long)cgi * (64 * ROWU64) + ci2 * ROWU64 + k * COT + c;
            s_wf[u * 2 + 0] = wt[(long)co * (Cc * Kk) + (2 * ci2) * Kk + k];
            s_wf[u * 2 + 1] = wt[(long)co * (Cc * Kk) + (2 * ci2 + 1) * Kk + k];
        }
    }
    __syncthreads();

    const ull* wbase = s_w + (long)cg * (64 * ROWU64);
    const int ci2lo = sp * CI2PER;
    const int cbs   = sp;            // producer co-block of this ci slice

    for (int s = 1; s < nq; s++) {
        const int q = q0 + s * dq;
        const float* prev = base + (long)(q - dq) * SQ;
        float*       cur  = base + (long)q * SQ;
        const long oBase = (long)(co0 + cg * COT) * CSTRIDE + p0 + pg * TP;

        // ---- prefetch cur_old (pass-stable; sp0 only) ----
        float4 oldv[COT][TP / 4];
        if (sp == 0) {
#pragma unroll
            for (int c = 0; c < COT; c++)
#pragma unroll
                for (int j = 0; j < TP / 4; j++)
                    oldv[c][j] = __ldcg(reinterpret_cast<const float4*>(
                        cur + oBase + (long)c * CSTRIDE + j * 4));
        }

        // ---- wait for this slice's producers (+ own CTA for s_red guard) ----
        if (s > 1 && gtid < 4) {
            const unsigned* f = nullptr;
            if (gtid < 3) {
                int pxn = px + gtid - 1;
                if (pxn >= 0 && pxn < npx) f = &g_flag[b][pxn][cbs][s - 1];
            } else {
                f = &g_flag[b][px][cby][s - 1];
            }
            if (f) {
                while (ld_cg_u32(f) == 0u) __nanosleep(20);
                __threadfence();
            }
        }
        group_bar(sp + 1, G);

        // ---- stage own ci2 slice of the window ----
        for (int t = gtid; t < CI2PER * SCH; t += G) {
            const int ci2 = ci2lo + t / SCH;
            const int c4  = t % SCH;
            const int p   = p0 - 4 + c4 * 4;
            const float* sa = prev + (long)(2 * ci2) * CSTRIDE + p;
            const float* sb = sa + CSTRIDE;
            float4 a, bb;
            if (p >= 0 && p + 4 <= L) {
                a  = __ldcg(reinterpret_cast<const float4*>(sa));
                bb = __ldcg(reinterpret_cast<const float4*>(sb));
            } else {
                a.x = (unsigned)(p+0) < (unsigned)L ? __ldcg(sa+0) : 0.f;
                a.y = (unsigned)(p+1) < (unsigned)L ? __ldcg(sa+1) : 0.f;
                a.z = (unsigned)(p+2) < (unsigned)L ? __ldcg(sa+2) : 0.f;
                a.w = (unsigned)(p+3) < (unsigned)L ? __ldcg(sa+3) : 0.f;
                bb.x = (unsigned)(p+0) < (unsigned)L ? __ldcg(sb+0) : 0.f;
                bb.y = (unsigned)(p+1) < (unsigned)L ? __ldcg(sb+1) : 0.f;
                bb.z = (unsigned)(p+2) < (unsigned)L ? __ldcg(sb+2) : 0.f;
                bb.w = (unsigned)(p+3) < (unsigned)L ? __ldcg(sb+3) : 0.f;
            }
            float4* s4 = reinterpret_cast<float4*>(s_in);
            const int f4i = (ci2 * WIN + c4 * 4) >> 1;
            s4[f4i + 0] = make_float4(a.x, bb.x, a.y, bb.y);
            s4[f4i + 1] = make_float4(a.z, bb.z, a.w, bb.w);
        }
        group_bar(sp + 1, G);

        // ---- register-tiled compute over own ci2 slice ----
        ull acc[COT][TP];
#pragma unroll
        for (int c = 0; c < COT; c++)
#pragma unroll
            for (int pt = 0; pt < TP; pt++) acc[c][pt] = 0ull;

#pragma unroll 2
        for (int i = 0; i < CI2PER; i++) {
            const int ci2 = ci2lo + i;
            ull win[NW];
            {
                const ulonglong2* w2 = reinterpret_cast<const ulonglong2*>(
                    s_in + (long)ci2 * WIN + pg * TP);
#pragma unroll
                for (int j = 0; j < NW / 2; j++) {
                    ulonglong2 t = w2[j];
                    win[2 * j] = t.x; win[2 * j + 1] = t.y;
                }
            }
            const ull* wrow = wbase + (long)ci2 * ROWU64;
#pragma unroll
            for (int k = 0; k < Kk; k++) {
                ulonglong2 w = *reinterpret_cast<const ulonglong2*>(wrow + k * 2);
#pragma unroll
                for (int pt = 0; pt < TP; pt++) {
                    fma2(acc[0][pt], w.x, win[pt + k]);
                    fma2(acc[1][pt], w.y, win[pt + k]);
                }
            }
        }

        // ---- fold lanes to floats; sp>0 deposit partials ----
        float f[ACCN];
#pragma unroll
        for (int c = 0; c < COT; c++)
#pragma unroll
            for (int pt = 0; pt < TP; pt++) {
                float2 t = unpack2(acc[c][pt]);
                f[c * TP + pt] = t.x + t.y;
            }
        if (sp > 0) {
            float* r = s_red + (long)((sp - 1) * G + gtid) * ACCN;
#pragma unroll
            for (int j = 0; j < ACCN / 4; j++)
                *reinterpret_cast<float4*>(r + j * 4) =
                    make_float4(f[j*4], f[j*4+1], f[j*4+2], f[j*4+3]);
        }
        __syncthreads();   // the ONLY CTA-wide barrier per step

        if (sp == 0) {
#pragma unroll
            for (int j = 0; j < SPLIT - 1; j++) {
                const float* r = s_red + (long)(j * G + gtid) * ACCN;
#pragma unroll
                for (int t = 0; t < ACCN / 4; t++) {
                    float4 rv = *reinterpret_cast<const float4*>(r + t * 4);
                    f[t*4]   += rv.x; f[t*4+1] += rv.y;
                    f[t*4+2] += rv.z; f[t*4+3] += rv.w;
                }
            }
            // ---- epilogue: cur = cur_old + relu(conv) ----
#pragma unroll
            for (int c = 0; c < COT; c++) {
                float* op = cur + oBase + (long)c * CSTRIDE;
#pragma unroll
                for (int j = 0; j < TP / 4; j++) {
                    float4 e;
                    e.x = oldv[c][j].x + fmaxf(f[c*TP + j*4 + 0], 0.f);
                    e.y = oldv[c][j].y + fmaxf(f[c*TP + j*4 + 1], 0.f);
                    e.z = oldv[c][j].z + fmaxf(f[c*TP + j*4 + 2], 0.f);
                    e.w = oldv[c][j].w + fmaxf(f[c*TP + j*4 + 3], 0.f);
                    *reinterpret_cast<float4*>(op + j * 4) = e;
                }
            }
            group_bar(1, G);
            if (tid == 0) {
                __threadfence();
                atomicExch(&g_flag[b][px][cby][s], 1u);
            }
        }
    }
}

// [b,c,R,C] -> [b,c,C,R], tiled 32x32.
__global__ __launch_bounds__(256)
void transpose_kernel(const float* __restrict__ src, float* __restrict__ dst,
                      int R, int C)
{
    __shared__ float t[32][33];
    const long plane = blockIdx.z;
    const float* s = src + plane * (long)R * C;
    float*       d = dst + plane * (long)R * C;
    const int c0 = blockIdx.x * 32, r0 = blockIdx.y * 32;
    const int x = threadIdx.x & 31, y = threadIdx.x >> 5;
#pragma unroll
    for (int i = 0; i < 32; i += 8)
        t[y + i][x] = s[(long)(r0 + y + i) * C + c0 + x];
    __syncthreads();
#pragma unroll
    for (int i = 0; i < 32; i += 8)
        d[(long)(c0 + y + i) * R + r0 + x] = t[x][y + i];
}

extern "C" void kernel_launch(void* const* d_in, const int* in_sizes, int n_in,
                              void* d_out, int out_size)
{
    const float* x       = (const float*)d_in[0];
    const float* w_down  = (const float*)d_in[1];
    const float* w_up    = (const float*)d_in[2];
    const float* w_right = (const float*)d_in[3];
    const float* w_left  = (const float*)d_in[4];
    float* out = (float*)d_out;

    // SMEM: weights 18432 u64 + window 64*WIN u64 + s_red floats
    const int SMEM_W = 18432 * 8 + 64 * 72 * 8 + 3 * 128 * 16 * 4;  // 208896
    const int SMEM_H = 18432 * 8 + 64 * 40 * 8 + 3 * 128 * 8 * 4;   // 180224
    cudaFuncSetAttribute((const void*)pass_kernel<8, 4>,
                         cudaFuncAttributeMaxDynamicSharedMemorySize, SMEM_W);
    cudaFuncSetAttribute((const void*)pass_kernel<4, 4>,
                         cudaFuncAttributeMaxDynamicSharedMemorySize, SMEM_H);

    void* flagp = nullptr; cudaGetSymbolAddress(&flagp, g_flag);
    void* tmpp  = nullptr; cudaGetSymbolAddress(&tmpp, g_tmp);
    float* tmp = (float*)tmpp;
    const size_t FLAG_BYTES = sizeof(unsigned) * Bb * 4 * 4 * 256;

    cudaMemcpyAsync(out, x, (size_t)Bb * BSTRIDE * sizeof(float),
                    cudaMemcpyDeviceToDevice);

    dim3 blk(512);
    dim3 gridW(Ww / 64, Cc / 32, Bb);   // conv along W: TP=8, PT=64
    dim3 gridH(Hh / 32, Cc / 32, Bb);   // conv along H: TP=4, PT=32

    // Pass 1: down. [b,c,h,w]: conv axis w (L=256), rec over h (SQ=256).
    cudaMemsetAsync(flagp, 0, FLAG_BYTES);
    pass_kernel<8, 4><<<gridW, blk, SMEM_W>>>(out, w_down, 0, +1, Hh, Ww, Ww);

    // Pass 2: up.
    cudaMemsetAsync(flagp, 0, FLAG_BYTES);
    pass_kernel<8, 4><<<gridW, blk, SMEM_W>>>(out, w_up, Hh - 1, -1, Hh, Ww, Ww);

    // Transpose to [b,c,w,h]
    transpose_kernel<<<dim3(Ww / 32, Hh / 32, Bb * Cc), dim3(256)>>>(out, tmp, Hh, Ww);

    // Pass 3: right. conv axis h (L=128), rec over w (SQ=128).
    cudaMemsetAsync(flagp, 0, FLAG_BYTES);
    pass_kernel<4, 4><<<gridH, blk, SMEM_H>>>(tmp, w_right, 0, +1, Ww, Hh, Hh);

    // Pass 4: left.
    cudaMemsetAsync(flagp, 0, FLAG_BYTES);
    pass_kernel<4, 4><<<gridH, blk, SMEM_H>>>(tmp, w_left, Ww - 1, -1, Ww, Hh, Hh);

    // Transpose back to [b,c,h,w]
    transpose_kernel<<<dim3(Hh / 32, Ww / 32, Bb * Cc), dim3(256)>>>(tmp, out, Ww, Hh);
}

// round 14
// speedup vs baseline: 2.0178x; 2.0117x over previous
#include <cuda_runtime.h>
#include <cuda_bf16.h>
#include <cstdint>

#define Cc 128
#define Hh 128
#define Ww 256
#define Bb 8
#define Kk 9
#define CSTRIDE (Hh * Ww)          // 32768
#define BSTRIDE (Cc * Hh * Ww)     // 4194304

// Per-(batch, px, step) completion counters (4 co-block CTAs each). Reset per pass.
__device__ unsigned g_cnt[Bb][4][256];
// Transposed-state scratch: [b][c][w][h]
__device__ float g_tmp[(size_t)Bb * BSTRIDE];

__device__ __forceinline__ unsigned ld_cg_u32(const unsigned* p) {
    unsigned v;
    asm volatile("ld.global.cg.u32 %0, [%1];" : "=r"(v) : "l"(p));
    return v;
}
// mma.sync m16n8k16 row.col f32.bf16.bf16.f32 (sm_80 path; fallback HMMA on sm_103)
__device__ __forceinline__ void mma16816(float* d, const uint32_t* a, const uint32_t* b) {
    asm volatile(
        "mma.sync.aligned.m16n8k16.row.col.f32.bf16.bf16.f32 "
        "{%0,%1,%2,%3}, {%4,%5,%6,%7}, {%8,%9}, {%0,%1,%2,%3};"
        : "+f"(d[0]), "+f"(d[1]), "+f"(d[2]), "+f"(d[3])
        : "r"(a[0]), "r"(a[1]), "r"(a[2]), "r"(a[3]), "r"(b[0]), "r"(b[1]));
}
// Split (a,b) into packed bf16 hi/lo words; low half = a (even ci), high = b (odd ci).
__device__ __forceinline__ void bfsplit2(float a, float b, uint32_t& hw, uint32_t& lw) {
    __nv_bfloat16 ha = __float2bfloat16(a), hb = __float2bfloat16(b);
    float ra = a - __bfloat162float(ha), rb = b - __bfloat162float(hb);
    __nv_bfloat16 la = __float2bfloat16(ra), lb = __float2bfloat16(rb);
    hw = (uint32_t)__bfloat16_as_ushort(ha) | ((uint32_t)__bfloat16_as_ushort(hb) << 16);
    lw = (uint32_t)__bfloat16_as_ushort(la) | ((uint32_t)__bfloat16_as_ushort(lb) << 16);
}

// Persistent directional pass using warp-level bf16 MMA, 3-term hi/lo split.
//
// K mapping (72 k16-tiles, no padding):
//   tiles t in [0,64): k_local 2c+par -> (ci = 2t+par, kk = c..): pairs along ci.
//     a0={W[m][2t][c],W[m][2t+1][c]}          b0={x[2t][j],x[2t+1][j]}, j=pf+g+c
//     a2=pair at kk=c+4                        b1=pair at kk=c+4
//   tiles t8 in [0,8) (tap kk=8): k_local 2c+par -> ci = 16 t8 + 2c + par.
// All fragment regs = aligned LDS.32 from ci-interleaved u32 arrays.
//
// CTA = (px, cby, b), 256 thr = 8 warps; warp w: mtile=w&1 (16 co),
// n-block=w>>1; NF n-frags of 8p each. Full K per warp (no reduction).
template <int PT, int NF>
__global__ __launch_bounds__(256, 1)
void pass_mma(float* __restrict__ state, const float* __restrict__ wt,
              int q0, int dq, int nq, int L, int SQ)
{
    constexpr int WWIN = PT + 20;          // u32 window words per ci2 (84 / 52)
    constexpr int RS2  = 516;              // A2 row stride (u32), bank-staggered
    constexpr int RS8  = 68;               // A8 row stride
    constexpr int A2N  = 32 * RS2;         // 16512
    constexpr int A8N  = 32 * RS8;         // 2176
    constexpr int WPN  = 64 * WWIN;
    constexpr int NCH  = WWIN / 4;         // staging float4 chunks per ci2

    extern __shared__ uint32_t smu[];
    uint32_t* A2h = smu;
    uint32_t* A2l = A2h + A2N;
    uint32_t* A8h = A2l + A2N;
    uint32_t* A8l = A8h + A8N;
    uint32_t* wpH = A8l + A8N;
    uint32_t* wpL = wpH + WPN;

    const int tid = threadIdx.x, wid = tid >> 5, lid = tid & 31;
    const int g = lid >> 2, c = lid & 3;
    const int mt = wid & 1, nb = wid >> 1;

    const int px = blockIdx.x, cby = blockIdx.y, b = blockIdx.z;
    const int p0 = px * PT, co0 = cby * 32;
    const int npx = gridDim.x;
    float* base = state + (size_t)b * BSTRIDE;

    // ---- stage weights (split + ci-pair packed) once per pass ----
    for (int idx = tid; idx < 32 * Cc * Kk; idx += 256) {
        int m = idx / (Cc * Kk), r = idx - m * (Cc * Kk);
        int ci = r / Kk, kk = r - ci * Kk;
        float f = wt[(size_t)(co0 + m) * (Cc * Kk) + r];
        __nv_bfloat16 h = __float2bfloat16(f);
        float rf = f - __bfloat162float(h);
        __nv_bfloat16 l = __float2bfloat16(rf);
        int ci2 = ci >> 1, par = ci & 1;
        if (kk < 8) {
            int u = m * RS2 + ci2 * 8 + kk;
            reinterpret_cast<__nv_bfloat16*>(A2h)[u * 2 + par] = h;
            reinterpret_cast<__nv_bfloat16*>(A2l)[u * 2 + par] = l;
        } else {
            int u = m * RS8 + ci2;
            reinterpret_cast<__nv_bfloat16*>(A8h)[u * 2 + par] = h;
            reinterpret_cast<__nv_bfloat16*>(A8l)[u * 2 + par] = l;
        }
    }
    __syncthreads();

    const int aB2 = (mt * 16 + g) * RS2 + c;
    const int aB8 = (mt * 16 + g) * RS8 + c;

    for (int s = 1; s < nq; s++) {
        // ---- wait for rows s-1 of p-blocks {px-1, px, px+1} (4 CTAs each) ----
        if (s > 1 && tid < 3) {
            int pxn = px + tid - 1;
            if (pxn >= 0 && pxn < npx) {
                const unsigned* f = &g_cnt[b][pxn][s - 1];
                while (ld_cg_u32(f) < 4u) __nanosleep(20);
            }
        }
        __syncthreads();
        __threadfence();   // acquire

        const float* prev = base + (size_t)(q0 + (s - 1) * dq) * SQ;
        float*       cur  = base + (size_t)(q0 + s * dq) * SQ;

        // ---- stage window: wp[ci2][j] = packed {x[2ci2][p], x[2ci2+1][p]}, p=p0-4+j ----
        for (int u = tid; u < 64 * NCH; u += 256) {
            int ci2 = u / NCH, j0 = (u - ci2 * NCH) * 4;
            int p = p0 - 4 + j0;
            const float* ra = prev + (size_t)(2 * ci2) * CSTRIDE;
            const float* rb = ra + CSTRIDE;
            float av[4], bv[4];
            if (p >= 0 && p + 4 <= L) {
                float4 va = __ldcg(reinterpret_cast<const float4*>(ra + p));
                float4 vb = __ldcg(reinterpret_cast<const float4*>(rb + p));
                av[0]=va.x; av[1]=va.y; av[2]=va.z; av[3]=va.w;
                bv[0]=vb.x; bv[1]=vb.y; bv[2]=vb.z; bv[3]=vb.w;
            } else {
#pragma unroll
                for (int j = 0; j < 4; j++) {
                    bool in = (unsigned)(p + j) < (unsigned)L;
                    av[j] = in ? __ldcg(ra + p + j) : 0.f;
                    bv[j] = in ? __ldcg(rb + p + j) : 0.f;
                }
            }
            uint32_t hw[4], lw[4];
#pragma unroll
            for (int j = 0; j < 4; j++) bfsplit2(av[j], bv[j], hw[j], lw[j]);
            *reinterpret_cast<uint4*>(wpH + ci2 * WWIN + j0) =
                make_uint4(hw[0], hw[1], hw[2], hw[3]);
            *reinterpret_cast<uint4*>(wpL + ci2 * WWIN + j0) =
                make_uint4(lw[0], lw[1], lw[2], lw[3]);
        }

        // ---- prefetch cur_old (exclusive region) ----
        float2 oldv[NF][2];
#pragma unroll
        for (int nf = 0; nf < NF; nf++) {
            int pf = nb * (8 * NF) + nf * 8;
            const float* r0 = cur + (size_t)(co0 + mt * 16 + g) * CSTRIDE
                                  + p0 + pf + 2 * c;
            oldv[nf][0] = __ldcg(reinterpret_cast<const float2*>(r0));
            oldv[nf][1] = __ldcg(reinterpret_cast<const float2*>(r0 + 8 * CSTRIDE));
        }
        __syncthreads();

        // ---- compute: full-K warp-level MMA, 3-term split ----
        float d[NF][4];
#pragma unroll
        for (int nf = 0; nf < NF; nf++)
#pragma unroll
            for (int j = 0; j < 4; j++) d[nf][j] = 0.f;

#pragma unroll 2
        for (int t = 0; t < 64; t++) {
            uint32_t ah[4], al[4];
            int ia = aB2 + t * 8;
            ah[0] = A2h[ia];     ah[1] = A2h[ia + 8 * RS2];
            ah[2] = A2h[ia + 4]; ah[3] = A2h[ia + 4 + 8 * RS2];
            al[0] = A2l[ia];     al[1] = A2l[ia + 8 * RS2];
            al[2] = A2l[ia + 4]; al[3] = A2l[ia + 4 + 8 * RS2];
#pragma unroll
            for (int nf = 0; nf < NF; nf++) {
                int jb = t * WWIN + nb * (8 * NF) + nf * 8 + g + c;
                uint32_t bh[2] = { wpH[jb], wpH[jb + 4] };
                uint32_t bl[2] = { wpL[jb], wpL[jb + 4] };
                mma16816(d[nf], ah, bh);
                mma16816(d[nf], ah, bl);
                mma16816(d[nf], al, bh);
            }
        }
#pragma unroll
        for (int t8 = 0; t8 < 8; t8++) {
            uint32_t ah[4], al[4];
            int ia = aB8 + t8 * 8;
            ah[0] = A8h[ia];     ah[1] = A8h[ia + 8 * RS8];
            ah[2] = A8h[ia + 4]; ah[3] = A8h[ia + 4 + 8 * RS8];
            al[0] = A8l[ia];     al[1] = A8l[ia + 8 * RS8];
            al[2] = A8l[ia + 4]; al[3] = A8l[ia + 4 + 8 * RS8];
#pragma unroll
            for (int nf = 0; nf < NF; nf++) {
                int jb = (8 * t8 + c) * WWIN + nb * (8 * NF) + nf * 8 + g + 8;
                uint32_t bh[2] = { wpH[jb], wpH[jb + 4 * WWIN] };
                uint32_t bl[2] = { wpL[jb], wpL[jb + 4 * WWIN] };
                mma16816(d[nf], ah, bh);
                mma16816(d[nf], ah, bl);
                mma16816(d[nf], al, bh);
            }
        }

        // ---- epilogue: cur = cur_old + relu(conv) ----
#pragma unroll
        for (int nf = 0; nf < NF; nf++) {
            int pf = nb * (8 * NF) + nf * 8;
            float* r0 = cur + (size_t)(co0 + mt * 16 + g) * CSTRIDE
                            + p0 + pf + 2 * c;
            float2 e0, e1;
            e0.x = oldv[nf][0].x + fmaxf(d[nf][0], 0.f);
            e0.y = oldv[nf][0].y + fmaxf(d[nf][1], 0.f);
            e1.x = oldv[nf][1].x + fmaxf(d[nf][2], 0.f);
            e1.y = oldv[nf][1].y + fmaxf(d[nf][3], 0.f);
            *reinterpret_cast<float2*>(r0)                = e0;
            *reinterpret_cast<float2*>(r0 + 8 * CSTRIDE)  = e1;
        }

        // ---- publish ----
        __syncthreads();
        if (tid == 0) {
            __threadfence();
            atomicAdd(&g_cnt[b][px][s], 1u);
        }
    }
}

// [b,c,R,C] -> [b,c,C,R], tiled 32x32.
__global__ __launch_bounds__(256)
void transpose_kernel(const float* __restrict__ src, float* __restrict__ dst,
                      int R, int C)
{
    __shared__ float t[32][33];
    const long plane = blockIdx.z;
    const float* s = src + plane * (long)R * C;
    float*       d = dst + plane * (long)R * C;
    const int c0 = blockIdx.x * 32, r0 = blockIdx.y * 32;
    const int x = threadIdx.x & 31, y = threadIdx.x >> 5;
#pragma unroll
    for (int i = 0; i < 32; i += 8)
        t[y + i][x] = s[(long)(r0 + y + i) * C + c0 + x];
    __syncthreads();
#pragma unroll
    for (int i = 0; i < 32; i += 8)
        d[(long)(c0 + y + i) * R + r0 + x] = t[x][y + i];
}

extern "C" void kernel_launch(void* const* d_in, const int* in_sizes, int n_in,
                              void* d_out, int out_size)
{
    const float* x       = (const float*)d_in[0];
    const float* w_down  = (const float*)d_in[1];
    const float* w_up    = (const float*)d_in[2];
    const float* w_right = (const float*)d_in[3];
    const float* w_left  = (const float*)d_in[4];
    float* out = (float*)d_out;

    // u32 counts: A2(2*16512) + A8(2*2176) + wp(2*64*WWIN)
    const int SMEM_W = (2 * 16512 + 2 * 2176 + 2 * 64 * 84) * 4;  // 192512
    const int SMEM_H = (2 * 16512 + 2 * 2176 + 2 * 64 * 52) * 4;  // 176128
    cudaFuncSetAttribute((const void*)pass_mma<64, 2>,
                         cudaFuncAttributeMaxDynamicSharedMemorySize, SMEM_W);
    cudaFuncSetAttribute((const void*)pass_mma<32, 1>,
                         cudaFuncAttributeMaxDynamicSharedMemorySize, SMEM_H);

    void *cntp, *tmpp;
    cudaGetSymbolAddress(&cntp, g_cnt);
    cudaGetSymbolAddress(&tmpp, g_tmp);
    float* tmp = (float*)tmpp;

    cudaMemcpyAsync(out, x, (size_t)Bb * BSTRIDE * sizeof(float),
                    cudaMemcpyDeviceToDevice);

    dim3 blk(256), grid(4, 4, Bb);

    // Pass 1: down. [b,c,h,w]: conv along w (L=256), rec over h (SQ=256).
    cudaMemsetAsync(cntp, 0, sizeof(g_cnt));
    pass_mma<64, 2><<<grid, blk, SMEM_W>>>(out, w_down, 0, +1, Hh, Ww, Ww);

    // Pass 2: up.
    cudaMemsetAsync(cntp, 0, sizeof(g_cnt));
    pass_mma<64, 2><<<grid, blk, SMEM_W>>>(out, w_up, Hh - 1, -1, Hh, Ww, Ww);

    // Transpose to [b,c,w,h]
    transpose_kernel<<<dim3(Ww / 32, Hh / 32, Bb * Cc), dim3(256)>>>(out, tmp, Hh, Ww);

    // Pass 3: right. conv along h (L=128), rec over w (SQ=128).
    cudaMemsetAsync(cntp, 0, sizeof(g_cnt));
    pass_mma<32, 1><<<grid, blk, SMEM_H>>>(tmp, w_right, 0, +1, Ww, Hh, Hh);

    // Pass 4: left.
    cudaMemsetAsync(cntp, 0, sizeof(g_cnt));
    pass_mma<32, 1><<<grid, blk, SMEM_H>>>(tmp, w_left, Ww - 1, -1, Ww, Hh, Hh);

    // Transpose back to [b,c,h,w]
    transpose_kernel<<<dim3(Hh / 32, Ww / 32, Bb * Cc), dim3(256)>>>(tmp, out, Ww, Hh);
}

// round 15
// speedup vs baseline: 2.2048x; 1.0927x over previous
#include <cuda_runtime.h>
#include <cuda_bf16.h>
#include <cstdint>

#define Cc 128
#define Hh 128
#define Ww 256
#define Bb 8
#define Kk 9
#define CSTRIDE (Hh * Ww)          // 32768
#define BSTRIDE (Cc * Hh * Ww)     // 4194304

// Per-(batch, px, step) completion counters (4 co-block CTAs each). Reset per pass.
__device__ unsigned g_cnt[Bb][4][256];
// Transposed-state scratch: [b][c][w][h]
__device__ float g_tmp[(size_t)Bb * BSTRIDE];

__device__ __forceinline__ unsigned ld_cg_u32(const unsigned* p) {
    unsigned v;
    asm volatile("ld.global.cg.u32 %0, [%1];" : "=r"(v) : "l"(p));
    return v;
}
// mma.sync m16n8k16 row.col f32.bf16.bf16.f32 (fallback HMMA on sm_103)
__device__ __forceinline__ void mma16816(float* d, const uint32_t* a, const uint32_t* b) {
    asm volatile(
        "mma.sync.aligned.m16n8k16.row.col.f32.bf16.bf16.f32 "
        "{%0,%1,%2,%3}, {%4,%5,%6,%7}, {%8,%9}, {%0,%1,%2,%3};"
        : "+f"(d[0]), "+f"(d[1]), "+f"(d[2]), "+f"(d[3])
        : "r"(a[0]), "r"(a[1]), "r"(a[2]), "r"(a[3]), "r"(b[0]), "r"(b[1]));
}
// Split (a,b) into packed bf16 hi/lo words; low half = a (even ci), high = b (odd ci).
__device__ __forceinline__ void bfsplit2(float a, float b, uint32_t& hw, uint32_t& lw) {
    __nv_bfloat16 ha = __float2bfloat16(a), hb = __float2bfloat16(b);
    float ra = a - __bfloat162float(ha), rb = b - __bfloat162float(hb);
    __nv_bfloat16 la = __float2bfloat16(ra), lb = __float2bfloat16(rb);
    hw = (uint32_t)__bfloat16_as_ushort(ha) | ((uint32_t)__bfloat16_as_ushort(hb) << 16);
    lw = (uint32_t)__bfloat16_as_ushort(la) | ((uint32_t)__bfloat16_as_ushort(lb) << 16);
}

// Persistent directional pass, warp-level bf16 MMA, 3-term hi/lo split.
// K mapping identical to R13 (proven): 64 ci-pair tiles + 8 tap-8 tiles.
// 512 thr = 16 warps = 2 mt x 4 nb x 2 ks; ks splits the k-tile range.
// Three accumulator sets (hh, hl, lh) give 3x MMA chain ILP; ks=1 warps
// deposit folded partials to SMEM, ks=0 warps reduce + epilogue.
template <int PT, int NF>
__global__ __launch_bounds__(512, 1)
void pass_mma(float* __restrict__ state, const float* __restrict__ wt,
              int q0, int dq, int nq, int L, int SQ)
{
    constexpr int WWIN = PT + 20;          // u32 window words per ci2 (84 / 52)
    constexpr int RS2  = 516;              // A2 row stride (u32)
    constexpr int RS8  = 68;               // A8 row stride
    constexpr int A2N  = 32 * RS2;         // 16512
    constexpr int A8N  = 32 * RS8;         // 2176
    constexpr int WPN  = 64 * WWIN;
    constexpr int NCH  = WWIN / 4;         // staging float4 chunks per ci2
    constexpr int AC   = NF * 4;           // accum floats per thread

    extern __shared__ uint32_t smu[];
    uint32_t* A2h = smu;
    uint32_t* A2l = A2h + A2N;
    uint32_t* A8h = A2l + A2N;
    uint32_t* A8l = A8h + A8N;
    uint32_t* wpH = A8l + A8N;
    uint32_t* wpL = wpH + WPN;
    float*    s_red = reinterpret_cast<float*>(wpL + WPN);  // [8 warp][32 lane][AC]

    const int tid = threadIdx.x, wid = tid >> 5, lid = tid & 31;
    const int g = lid >> 2, c = lid & 3;
    const int mt = wid & 1, nb = (wid >> 1) & 3, ks = wid >> 3;

    const int px = blockIdx.x, cby = blockIdx.y, b = blockIdx.z;
    const int p0 = px * PT, co0 = cby * 32;
    const int npx = gridDim.x;
    float* base = state + (size_t)b * BSTRIDE;

    // ---- stage weights (split + ci-pair packed) once per pass ----
    for (int idx = tid; idx < 32 * Cc * Kk; idx += 512) {
        int m = idx / (Cc * Kk), r = idx - m * (Cc * Kk);
        int ci = r / Kk, kk = r - ci * Kk;
        float f = wt[(size_t)(co0 + m) * (Cc * Kk) + r];
        __nv_bfloat16 h = __float2bfloat16(f);
        float rf = f - __bfloat162float(h);
        __nv_bfloat16 l = __float2bfloat16(rf);
        int ci2 = ci >> 1, par = ci & 1;
        if (kk < 8) {
            int u = m * RS2 + ci2 * 8 + kk;
            reinterpret_cast<__nv_bfloat16*>(A2h)[u * 2 + par] = h;
            reinterpret_cast<__nv_bfloat16*>(A2l)[u * 2 + par] = l;
        } else {
            int u = m * RS8 + ci2;
            reinterpret_cast<__nv_bfloat16*>(A8h)[u * 2 + par] = h;
            reinterpret_cast<__nv_bfloat16*>(A8l)[u * 2 + par] = l;
        }
    }
    __syncthreads();

    const int aB2 = (mt * 16 + g) * RS2 + c;
    const int aB8 = (mt * 16 + g) * RS8 + c;

    for (int s = 1; s < nq; s++) {
        // ---- wait for rows s-1 of p-blocks {px-1, px, px+1} (4 CTAs each) ----
        if (s > 1 && tid < 3) {
            int pxn = px + tid - 1;
            if (pxn >= 0 && pxn < npx) {
                const unsigned* f = &g_cnt[b][pxn][s - 1];
                while (ld_cg_u32(f) < 4u) __nanosleep(20);
            }
        }
        __syncthreads();
        __threadfence();   // acquire

        const float* prev = base + (size_t)(q0 + (s - 1) * dq) * SQ;
        float*       cur  = base + (size_t)(q0 + s * dq) * SQ;

        // ---- stage window: wp[ci2][j] = packed {x[2ci2][p], x[2ci2+1][p]} ----
        for (int u = tid; u < 64 * NCH; u += 512) {
            int ci2 = u / NCH, j0 = (u - ci2 * NCH) * 4;
            int p = p0 - 4 + j0;
            const float* ra = prev + (size_t)(2 * ci2) * CSTRIDE;
            const float* rb = ra + CSTRIDE;
            float av[4], bv[4];
            if (p >= 0 && p + 4 <= L) {
                float4 va = __ldcg(reinterpret_cast<const float4*>(ra + p));
                float4 vb = __ldcg(reinterpret_cast<const float4*>(rb + p));
                av[0]=va.x; av[1]=va.y; av[2]=va.z; av[3]=va.w;
                bv[0]=vb.x; bv[1]=vb.y; bv[2]=vb.z; bv[3]=vb.w;
            } else {
#pragma unroll
                for (int j = 0; j < 4; j++) {
                    bool in = (unsigned)(p + j) < (unsigned)L;
                    av[j] = in ? __ldcg(ra + p + j) : 0.f;
                    bv[j] = in ? __ldcg(rb + p + j) : 0.f;
                }
            }
            uint32_t hw[4], lw[4];
#pragma unroll
            for (int j = 0; j < 4; j++) bfsplit2(av[j], bv[j], hw[j], lw[j]);
            *reinterpret_cast<uint4*>(wpH + ci2 * WWIN + j0) =
                make_uint4(hw[0], hw[1], hw[2], hw[3]);
            *reinterpret_cast<uint4*>(wpL + ci2 * WWIN + j0) =
                make_uint4(lw[0], lw[1], lw[2], lw[3]);
        }

        // ---- prefetch cur_old (ks=0 warps only; exclusive region) ----
        float2 oldv[NF][2];
        if (ks == 0) {
#pragma unroll
            for (int nf = 0; nf < NF; nf++) {
                int pf = nb * (8 * NF) + nf * 8;
                const float* r0 = cur + (size_t)(co0 + mt * 16 + g) * CSTRIDE
                                      + p0 + pf + 2 * c;
                oldv[nf][0] = __ldcg(reinterpret_cast<const float2*>(r0));
                oldv[nf][1] = __ldcg(reinterpret_cast<const float2*>(r0 + 8 * CSTRIDE));
            }
        }
        __syncthreads();

        // ---- compute: half-K per warp, 3 independent accumulator sets ----
        float dhh[NF][4], dhl[NF][4], dlh[NF][4];
#pragma unroll
        for (int nf = 0; nf < NF; nf++)
#pragma unroll
            for (int j = 0; j < 4; j++) {
                dhh[nf][j] = 0.f; dhl[nf][j] = 0.f; dlh[nf][j] = 0.f;
            }

#pragma unroll 2
        for (int tt = 0; tt < 32; tt++) {
            const int t = ks * 32 + tt;
            uint32_t ah[4], al[4];
            int ia = aB2 + t * 8;
            ah[0] = A2h[ia];     ah[1] = A2h[ia + 8 * RS2];
            ah[2] = A2h[ia + 4]; ah[3] = A2h[ia + 4 + 8 * RS2];
            al[0] = A2l[ia];     al[1] = A2l[ia + 8 * RS2];
            al[2] = A2l[ia + 4]; al[3] = A2l[ia + 4 + 8 * RS2];
#pragma unroll
            for (int nf = 0; nf < NF; nf++) {
                int jb = t * WWIN + nb * (8 * NF) + nf * 8 + g + c;
                uint32_t bh[2] = { wpH[jb], wpH[jb + 4] };
                uint32_t bl[2] = { wpL[jb], wpL[jb + 4] };
                mma16816(dhh[nf], ah, bh);
                mma16816(dhl[nf], ah, bl);
                mma16816(dlh[nf], al, bh);
            }
        }
#pragma unroll
        for (int t8i = 0; t8i < 4; t8i++) {
            const int t8 = ks * 4 + t8i;
            uint32_t ah[4], al[4];
            int ia = aB8 + t8 * 8;
            ah[0] = A8h[ia];     ah[1] = A8h[ia + 8 * RS8];
            ah[2] = A8h[ia + 4]; ah[3] = A8h[ia + 4 + 8 * RS8];
            al[0] = A8l[ia];     al[1] = A8l[ia + 8 * RS8];
            al[2] = A8l[ia + 4]; al[3] = A8l[ia + 4 + 8 * RS8];
#pragma unroll
            for (int nf = 0; nf < NF; nf++) {
                int jb = (8 * t8 + c) * WWIN + nb * (8 * NF) + nf * 8 + g + 8;
                uint32_t bh[2] = { wpH[jb], wpH[jb + 4 * WWIN] };
                uint32_t bl[2] = { wpL[jb], wpL[jb + 4 * WWIN] };
                mma16816(dhh[nf], ah, bh);
                mma16816(dhl[nf], ah, bl);
                mma16816(dlh[nf], al, bh);
            }
        }

        // ---- fold terms; ks=1 deposit partials ----
        float d[NF][4];
#pragma unroll
        for (int nf = 0; nf < NF; nf++)
#pragma unroll
            for (int j = 0; j < 4; j++)
                d[nf][j] = dhh[nf][j] + dhl[nf][j] + dlh[nf][j];

        if (ks == 1) {
            float* r = s_red + ((mt * 4 + nb) * 32 + lid) * AC;
#pragma unroll
            for (int nf = 0; nf < NF; nf++)
                *reinterpret_cast<float4*>(r + nf * 4) =
                    make_float4(d[nf][0], d[nf][1], d[nf][2], d[nf][3]);
        }
        __syncthreads();

        if (ks == 0) {
            const float* r = s_red + ((mt * 4 + nb) * 32 + lid) * AC;
#pragma unroll
            for (int nf = 0; nf < NF; nf++) {
                float4 rv = *reinterpret_cast<const float4*>(r + nf * 4);
                d[nf][0] += rv.x; d[nf][1] += rv.y;
                d[nf][2] += rv.z; d[nf][3] += rv.w;
            }
            // ---- epilogue: cur = cur_old + relu(conv) ----
#pragma unroll
            for (int nf = 0; nf < NF; nf++) {
                int pf = nb * (8 * NF) + nf * 8;
                float* r0 = cur + (size_t)(co0 + mt * 16 + g) * CSTRIDE
                                + p0 + pf + 2 * c;
                float2 e0, e1;
                e0.x = oldv[nf][0].x + fmaxf(d[nf][0], 0.f);
                e0.y = oldv[nf][0].y + fmaxf(d[nf][1], 0.f);
                e1.x = oldv[nf][1].x + fmaxf(d[nf][2], 0.f);
                e1.y = oldv[nf][1].y + fmaxf(d[nf][3], 0.f);
                *reinterpret_cast<float2*>(r0)               = e0;
                *reinterpret_cast<float2*>(r0 + 8 * CSTRIDE) = e1;
            }
        }

        // ---- publish ----
        __syncthreads();
        if (tid == 0) {
            __threadfence();
            atomicAdd(&g_cnt[b][px][s], 1u);
        }
    }
}

// [b,c,R,C] -> [b,c,C,R], tiled 32x32.
__global__ __launch_bounds__(256)
void transpose_kernel(const float* __restrict__ src, float* __restrict__ dst,
                      int R, int C)
{
    __shared__ float t[32][33];
    const long plane = blockIdx.z;
    const float* s = src + plane * (long)R * C;
    float*       d = dst + plane * (long)R * C;
    const int c0 = blockIdx.x * 32, r0 = blockIdx.y * 32;
    const int x = threadIdx.x & 31, y = threadIdx.x >> 5;
#pragma unroll
    for (int i = 0; i < 32; i += 8)
        t[y + i][x] = s[(long)(r0 + y + i) * C + c0 + x];
    __syncthreads();
#pragma unroll
    for (int i = 0; i < 32; i += 8)
        d[(long)(c0 + y + i) * R + r0 + x] = t[x][y + i];
}

extern "C" void kernel_launch(void* const* d_in, const int* in_sizes, int n_in,
                              void* d_out, int out_size)
{
    const float* x       = (const float*)d_in[0];
    const float* w_down  = (const float*)d_in[1];
    const float* w_up    = (const float*)d_in[2];
    const float* w_right = (const float*)d_in[3];
    const float* w_left  = (const float*)d_in[4];
    float* out = (float*)d_out;

    // u32 counts: A2(2*16512) + A8(2*2176) + wp(2*64*WWIN) + s_red
    const int SMEM_W = (2 * 16512 + 2 * 2176 + 2 * 64 * 84) * 4 + 8 * 32 * 8 * 4;  // 200704
    const int SMEM_H = (2 * 16512 + 2 * 2176 + 2 * 64 * 52) * 4 + 8 * 32 * 4 * 4;  // 180224
    cudaFuncSetAttribute((const void*)pass_mma<64, 2>,
                         cudaFuncAttributeMaxDynamicSharedMemorySize, SMEM_W);
    cudaFuncSetAttribute((const void*)pass_mma<32, 1>,
                         cudaFuncAttributeMaxDynamicSharedMemorySize, SMEM_H);

    void *cntp, *tmpp;
    cudaGetSymbolAddress(&cntp, g_cnt);
    cudaGetSymbolAddress(&tmpp, g_tmp);
    float* tmp = (float*)tmpp;

    cudaMemcpyAsync(out, x, (size_t)Bb * BSTRIDE * sizeof(float),
                    cudaMemcpyDeviceToDevice);

    dim3 blk(512), grid(4, 4, Bb);

    // Pass 1: down. [b,c,h,w]: conv along w (L=256), rec over h (SQ=256).
    cudaMemsetAsync(cntp, 0, sizeof(g_cnt));
    pass_mma<64, 2><<<grid, blk, SMEM_W>>>(out, w_down, 0, +1, Hh, Ww, Ww);

    // Pass 2: up.
    cudaMemsetAsync(cntp, 0, sizeof(g_cnt));
    pass_mma<64, 2><<<grid, blk, SMEM_W>>>(out, w_up, Hh - 1, -1, Hh, Ww, Ww);

    // Transpose to [b,c,w,h]
    transpose_kernel<<<dim3(Ww / 32, Hh / 32, Bb * Cc), dim3(256)>>>(out, tmp, Hh, Ww);

    // Pass 3: right. conv along h (L=128), rec over w (SQ=128).
    cudaMemsetAsync(cntp, 0, sizeof(g_cnt));
    pass_mma<32, 1><<<grid, blk, SMEM_H>>>(tmp, w_right, 0, +1, Ww, Hh, Hh);

    // Pass 4: left.
    cudaMemsetAsync(cntp, 0, sizeof(g_cnt));
    pass_mma<32, 1><<<grid, blk, SMEM_H>>>(tmp, w_left, Ww - 1, -1, Ww, Hh, Hh);

    // Transpose back to [b,c,h,w]
    transpose_kernel<<<dim3(Hh / 32, Ww / 32, Bb * Cc), dim3(256)>>>(tmp, out, Ww, Hh);
}